// round 12
// baseline (speedup 1.0000x reference)
#include <cuda_runtime.h>
#include <cuda_fp16.h>
#include <cstdint>

// ---------------- problem constants ----------------
#define NN      65536
#define CC      256
#define BB      8
#define EMBD    512
#define NET     7
#define EE      458752
#define WROW    263
#define EPSV    1e-5f
#define NT7     (NN * NET)

// ---------------- device scratch ----------------
__device__ __align__(256) __half   g_hH[(size_t)(NN + 1) * CC];   // h row-major fp16 (+1 zero row)
__device__ __align__(256) uint32_t g_WtB[(size_t)NET * 32 * 16 * 32 * 2]; // B fp16 fragments
__device__ __align__(256) __half   g_Yh[(size_t)NT7 * CC];        // compact Y fp16 (worst case)
__device__ __align__(256) float    g_out1[(size_t)NN * CC];
__device__ float    g_S1[BB * CC];
__device__ float    g_S2[BB * CC];
__device__ float    g_cnt[BB];
__device__ float    g_mg[BB * 32];
__device__ float    g_istd[BB * 32];
__device__ __align__(256) float    g_emb[BB * CC];
__device__ int      g_deg[NN];
__device__ int      g_off[NN + 1];
__device__ int      g_cur[NN];
__device__ unsigned g_epack[EE];
// compaction structures
__device__ int      g_used[NT7];
__device__ int      g_pos[NT7];
__device__ int      g_rowmap[NT7];
__device__ int      g_bsum[448];
__device__ int      g_bbase[448];
__device__ int      g_tbase[8];
__device__ int      g_Mtot;

// ---------------- helpers ----------------
__device__ __forceinline__ float silu(float y) {
    return y / (1.f + __expf(-y));
}

__device__ __forceinline__ uint32_t smem_u32(const void* p) {
    uint32_t a;
    asm("{ .reg .u64 t; cvta.to.shared.u64 t, %1; cvt.u32.u64 %0, t; }" : "=r"(a) : "l"(p));
    return a;
}

__device__ __forceinline__ void cp16(uint32_t dst, const void* src) {
    asm volatile("cp.async.cg.shared.global [%0], [%1], 16;\n" :: "r"(dst), "l"(src));
}
__device__ __forceinline__ void cp_commit() { asm volatile("cp.async.commit_group;\n" ::: "memory"); }
__device__ __forceinline__ void cp_wait1()  { asm volatile("cp.async.wait_group 1;\n" ::: "memory"); }
__device__ __forceinline__ void cp_wait0()  { asm volatile("cp.async.wait_group 0;\n" ::: "memory"); }

__device__ __forceinline__ void mma_f16(float c[4], uint32_t a0, uint32_t a1,
                                        uint32_t a2, uint32_t a3,
                                        uint32_t b0, uint32_t b1) {
    asm volatile(
        "mma.sync.aligned.m16n8k16.row.col.f32.f16.f16.f32 "
        "{%0,%1,%2,%3}, {%4,%5,%6,%7}, {%8,%9}, {%0,%1,%2,%3};\n"
        : "+f"(c[0]), "+f"(c[1]), "+f"(c[2]), "+f"(c[3])
        : "r"(a0), "r"(a1), "r"(a2), "r"(a3), "r"(b0), "r"(b1));
}

// ---------------- zero / CSR / compaction kernels ----------------

__global__ void k_zero_all() {
    int i = blockIdx.x * blockDim.x + threadIdx.x;
    if (i < NT7)     { g_used[i] = 0; g_rowmap[i] = NN; }
    if (i < NN)      g_deg[i] = 0;
    if (i < BB * CC) { g_S1[i] = 0.f; g_S2[i] = 0.f; }
    if (i < BB)      g_cnt[i] = 0.f;
    if (i < 128)     ((uint32_t*)(g_hH + (size_t)NN * CC))[i] = 0;   // zero row
}

// merged degree count + used-pair mark (single edge pass)
__global__ void k_degmark(const int* __restrict__ ei, const int* __restrict__ et) {
    int e = blockIdx.x * blockDim.x + threadIdx.x;
    if (e >= EE) return;
    atomicAdd(&g_deg[ei[e]], 1);
    g_used[et[e] * NN + ei[EE + e]] = 1;
}

// stage A: per-1024-block sums of used flags (448 blocks)
__global__ void k_scanA() {
    __shared__ int sh[256];
    int b = blockIdx.x, tid = threadIdx.x;
    int base = b * 1024 + tid * 4;
    int s = g_used[base] + g_used[base + 1] + g_used[base + 2] + g_used[base + 3];
    sh[tid] = s;
    __syncthreads();
    for (int o = 128; o > 0; o >>= 1) {
        if (tid < o) sh[tid] += sh[tid + o];
        __syncthreads();
    }
    if (tid == 0) g_bsum[b] = sh[0];
}

// stage B (parallel): per-type block-base scan + padded type bases (1 block, 448 thr)
__global__ void k_scanB() {
    __shared__ int sh[448];
    __shared__ int tsum[NET];
    int tid = threadIdx.x;          // 0..447
    int t = tid >> 6, l = tid & 63;
    int v = g_bsum[tid];
    sh[tid] = v;
    __syncthreads();
    for (int o = 1; o < 64; o <<= 1) {
        int u = (l >= o) ? sh[tid - o] : 0;
        __syncthreads();
        sh[tid] += u;
        __syncthreads();
    }
    if (l == 63) tsum[t] = sh[tid];
    __syncthreads();
    if (tid == 0) {
        int mt = 0;
#pragma unroll
        for (int tt = 0; tt < NET; tt++) {
            g_tbase[tt] = mt;
            mt += (tsum[tt] + 127) & ~127;
        }
        g_tbase[NET] = mt;
        g_Mtot = mt;
    }
    g_bbase[tid] = sh[tid] - v;     // exclusive within type group
}

// stage C: per-element positions + rowmap
__global__ void k_scanC() {
    __shared__ int sh[256];
    int b = blockIdx.x, tid = threadIdx.x, t = b >> 6;
    int base = b * 1024 + tid * 4;
    int f0 = g_used[base], f1 = g_used[base + 1], f2 = g_used[base + 2], f3 = g_used[base + 3];
    int s = f0 + f1 + f2 + f3;
    sh[tid] = s;
    __syncthreads();
    for (int o = 1; o < 256; o <<= 1) {
        int v = (tid >= o) ? sh[tid - o] : 0;
        __syncthreads();
        sh[tid] += v;
        __syncthreads();
    }
    int run = g_bbase[b] + ((tid == 0) ? 0 : sh[tid - 1]);
    int tb = g_tbase[t];
    int cbase = base - t * NN;
    if (f0) { g_pos[base]     = run; g_rowmap[tb + run] = cbase;     run++; }
    if (f1) { g_pos[base + 1] = run; g_rowmap[tb + run] = cbase + 1; run++; }
    if (f2) { g_pos[base + 2] = run; g_rowmap[tb + run] = cbase + 2; run++; }
    if (f3) { g_pos[base + 3] = run; g_rowmap[tb + run] = cbase + 3; run++; }
}

// scan destination-row degrees -> CSR offsets
__global__ void k_scan() {
    __shared__ int ps[1024];
    int t = threadIdx.x;
    int s = 0;
#pragma unroll 8
    for (int i = 0; i < 64; i++) s += g_deg[t * 64 + i];
    ps[t] = s;
    __syncthreads();
    for (int off = 1; off < 1024; off <<= 1) {
        int v = (t >= off) ? ps[t - off] : 0;
        __syncthreads();
        ps[t] += v;
        __syncthreads();
    }
    int run = (t == 0) ? 0 : ps[t - 1];
    for (int i = 0; i < 64; i++) {
        int d = g_deg[t * 64 + i];
        g_off[t * 64 + i] = run;
        g_cur[t * 64 + i] = run;
        run += d;
    }
    if (t == 1023) g_off[NN] = run;
}

// fill CSR payload: gpos(19b) | t(3b) | nt(3b)
__global__ void k_fill(const int* __restrict__ ei, const int* __restrict__ et,
                       const int* __restrict__ ntp) {
    int e = blockIdx.x * blockDim.x + threadIdx.x;
    if (e >= EE) return;
    int r = ei[e];
    int c = ei[EE + e];
    int t = et[e];
    int nt = ntp[c];
    int gpos = g_tbase[t] + g_pos[t * NN + c];
    int pos = atomicAdd(&g_cur[r], 1);
    g_epack[pos] = (unsigned)gpos | ((unsigned)t << 19) | ((unsigned)nt << 22);
}

__global__ void k_emb(const float* __restrict__ emb, const float* __restrict__ ew,
                      const float* __restrict__ eb) {
    __shared__ float se[EMBD];
    int b = blockIdx.x;
    int j = threadIdx.x;
    for (int k = j; k < EMBD; k += 256) se[k] = silu(emb[b * EMBD + k]);
    __syncthreads();
    float acc = eb[j];
#pragma unroll 8
    for (int k = 0; k < EMBD; k++) acc = fmaf(se[k], ew[k * CC + j], acc);
    g_emb[b * CC + j] = acc;
}

__global__ void k_stats(const float* __restrict__ src, int use_out1,
                        const int* __restrict__ bid, int do_cnt) {
    const float* s = use_out1 ? g_out1 : src;
    int c = threadIdx.x;
    int r0 = blockIdx.x * 64;
    float s1 = 0.f, s2 = 0.f;
    int cb = bid[r0];
    int cl = 0;
    for (int i = 0; i < 64; i++) {
        int r = r0 + i;
        int b = bid[r];
        if (b != cb) {
            atomicAdd(&g_S1[cb * CC + c], s1);
            atomicAdd(&g_S2[cb * CC + c], s2);
            if (do_cnt && c == 0) atomicAdd(&g_cnt[cb], (float)cl);
            s1 = 0.f; s2 = 0.f; cl = 0; cb = b;
        }
        float v = s[(size_t)r * CC + c];
        s1 += v;
        s2 = fmaf(v, v, s2);
        cl++;
    }
    atomicAdd(&g_S1[cb * CC + c], s1);
    atomicAdd(&g_S2[cb * CC + c], s2);
    if (do_cnt && c == 0) atomicAdd(&g_cnt[cb], (float)cl);
}

// finalize group stats; re-zero S1/S2 for the next pass (saves a launch)
__global__ void k_fin() {
    int t = threadIdx.x;
    int b = t >> 5, g = t & 31;
    float gs1 = 0.f, gs2 = 0.f;
#pragma unroll
    for (int i = 0; i < 8; i++) {
        gs1 += g_S1[b * CC + g * 8 + i];
        gs2 += g_S2[b * CC + g * 8 + i];
    }
    float n = g_cnt[b] * 8.f;
    float inv = 1.f / (n + EPSV);
    float m = gs1 * inv;
    float var = (gs2 - 2.f * m * gs1 + n * m * m) * inv;
    g_mg[b * 32 + g] = m;
    g_istd[b * 32 + g] = rsqrtf(var + EPSV);
#pragma unroll
    for (int i = 0; i < 8; i++) {
        g_S1[b * CC + g * 8 + i] = 0.f;
        g_S2[b * CC + g * 8 + i] = 0.f;
    }
}

// h = fp16( silu( gn(x) ) ), row-major
__global__ void k_norm(const float* __restrict__ src, int use_out1,
                       const int* __restrict__ bid, const float* __restrict__ w,
                       const float* __restrict__ bbv) {
    const float* sp = use_out1 ? g_out1 : src;
    int n = blockIdx.x * 2 + (threadIdx.x >> 7);
    int cp2 = threadIdx.x & 127;
    int c0 = cp2 * 2;
    int b = bid[n];
    int g = c0 >> 3;
    float m = g_mg[b * 32 + g];
    float is = g_istd[b * 32 + g];
    float2 v = *(const float2*)(sp + (size_t)n * CC + c0);
    float y0 = silu((v.x - m) * is * w[c0] + bbv[c0]);
    float y1 = silu((v.y - m) * is * w[c0 + 1] + bbv[c0 + 1]);
    ((__half2*)g_hH)[(size_t)n * 128 + cp2] = __floats2half2_rn(y0, y1);
}

// W[t][k][n] -> fp16 B-fragment layout
__global__ void k_wt(const float* __restrict__ W) {
    int g = blockIdx.x * blockDim.x + threadIdx.x;
    if (g >= NET * 32 * 16 * 32 * 2) return;
    int breg = g & 1;
    int lane = (g >> 1) & 31;
    int kt = (g >> 6) & 15;
    int nt = (g >> 10) & 31;
    int t = g >> 15;
    int k = kt * 16 + (lane & 3) * 2 + breg * 8;
    int n = nt * 8 + (lane >> 2);
    float v0 = W[(size_t)(t * WROW + k) * CC + n];
    float v1 = W[(size_t)(t * WROW + k + 1) * CC + n];
    __half2 h2 = __floats2half2_rn(v0, v1);
    g_WtB[(size_t)g] = *(uint32_t*)&h2;
}

// -------- compacted fp16 GEMM (R9 form: simple Y epilogue) --------
#define GEMM_SMEM 66048

__device__ __forceinline__ void cpA(uint4* sA, const int* __restrict__ srow, int kc, int tid) {
#pragma unroll
    for (int i = 0; i < 4; i++) {
        int idx = i * 256 + tid;
        int r = idx >> 3, u = idx & 7;
        const __half* src = g_hH + (size_t)srow[r] * CC + kc * 64 + u * 8;
        cp16(smem_u32(sA + r * 8 + (u ^ (r & 7))), src);
    }
}

__device__ __forceinline__ void cpB(uint32_t* sB, const uint32_t* gB, int c, int tid) {
#pragma unroll
    for (int i = 0; i < 4; i++) {
        int idx = i * 256 + tid;
        int nt = idx >> 6, rest = idx & 63;
        int ktl = rest >> 4, u = rest & 15;
        const uint32_t* src = gB + ((size_t)nt * 16 + c * 4 + ktl) * 64 + u * 4;
        cp16(smem_u32(sB + ((nt * 4 + ktl) * 64 + u * 4)), src);
    }
}

__device__ __forceinline__ void compute_chunk(const uint4* sA, const uint32_t* sB,
                                              float c[2][8][4], int wm, int wn, int lane) {
#pragma unroll
    for (int ktl = 0; ktl < 4; ktl++) {
        uint32_t a[2][4];
#pragma unroll
        for (int mm = 0; mm < 2; mm++) {
            int r = wm * 32 + mm * 16 + (lane & 15);
            int grp = (ktl * 2 + (lane >> 4)) ^ (r & 7);
            uint32_t addr = smem_u32(sA + r * 8 + grp);
            asm volatile("ldmatrix.sync.aligned.m8n8.x4.shared.b16 {%0,%1,%2,%3}, [%4];"
                         : "=r"(a[mm][0]), "=r"(a[mm][1]), "=r"(a[mm][2]), "=r"(a[mm][3])
                         : "r"(addr));
        }
#pragma unroll
        for (int nn = 0; nn < 8; nn++) {
            uint2 b = *(const uint2*)(sB + ((wn * 8 + nn) * 4 + ktl) * 64 + lane * 2);
            mma_f16(c[0][nn], a[0][0], a[0][1], a[0][2], a[0][3], b.x, b.y);
            mma_f16(c[1][nn], a[1][0], a[1][1], a[1][2], a[1][3], b.x, b.y);
        }
    }
}

__global__ void __launch_bounds__(256, 2) k_gemm() {
    extern __shared__ uint32_t sm[];
    uint4*    A0 = (uint4*)sm;             // 16KB
    uint4*    A1 = (uint4*)(sm + 4096);    // 16KB
    uint32_t* B0 = sm + 8192;              // 16KB
    uint32_t* B1 = sm + 12288;             // 16KB
    int*      srow = (int*)(sm + 16384);   // 512B

    int m0 = blockIdx.y * 128;
    if (m0 >= g_Mtot) return;
    int t = 0;
    while (m0 >= g_tbase[t + 1]) t++;

    int tid = threadIdx.x;
    int lane = tid & 31, warp = tid >> 5;
    int wm = warp & 3, wn = warp >> 2;
    int ntile = blockIdx.x;
    int n0 = ntile * 128;

    if (tid < 128) srow[tid] = g_rowmap[m0 + tid];
    __syncthreads();

    const uint32_t* gB = g_WtB + ((size_t)t * 32 + ntile * 16) * 16 * 64;

    float c[2][8][4];
#pragma unroll
    for (int mm = 0; mm < 2; mm++)
#pragma unroll
        for (int nn = 0; nn < 8; nn++)
#pragma unroll
            for (int q = 0; q < 4; q++) c[mm][nn][q] = 0.f;

    cpA(A0, srow, 0, tid); cpB(B0, gB, 0, tid); cp_commit();
    cpA(A1, srow, 1, tid); cpB(B1, gB, 1, tid); cp_commit();

    cp_wait1(); __syncthreads();
    compute_chunk(A0, B0, c, wm, wn, lane);
    __syncthreads();
    cpA(A0, srow, 2, tid); cpB(B0, gB, 2, tid); cp_commit();

    cp_wait1(); __syncthreads();
    compute_chunk(A1, B1, c, wm, wn, lane);
    __syncthreads();
    cpA(A1, srow, 3, tid); cpB(B1, gB, 3, tid); cp_commit();

    cp_wait1(); __syncthreads();
    compute_chunk(A0, B0, c, wm, wn, lane);

    cp_wait0(); __syncthreads();
    compute_chunk(A1, B1, c, wm, wn, lane);

    // epilogue -> compact fp16 Y
    int gid = lane >> 2, tig = lane & 3;
    __half* Yb = g_Yh + (size_t)m0 * CC + n0;
#pragma unroll
    for (int mm = 0; mm < 2; mm++) {
#pragma unroll
        for (int nn = 0; nn < 8; nn++) {
            int r = wm * 32 + mm * 16 + gid;
            int cc2 = wn * 64 + nn * 8 + tig * 2;
            *(__half2*)(Yb + (size_t)r * CC + cc2)       = __floats2half2_rn(c[mm][nn][0], c[mm][nn][1]);
            *(__half2*)(Yb + (size_t)(r + 8) * CC + cc2) = __floats2half2_rn(c[mm][nn][2], c[mm][nn][3]);
        }
    }
}

// warp-per-node gather; epack preloaded lane-parallel, 2 edges per iter (MLP)
__device__ __forceinline__ void gacc(unsigned p, const float* __restrict__ W,
                                     int lane, float a[8]) {
    int gpos = p & 0x7FFFF;
    int t = (p >> 19) & 7;
    int nt = (p >> 22) & 7;
    uint4 v = __ldg((const uint4*)(g_Yh + (size_t)gpos * CC) + lane);
    const float* wr = W + (size_t)(t * WROW + CC + nt) * CC + lane * 8;
    float4 w0 = *(const float4*)wr;
    float4 w1 = *(const float4*)(wr + 4);
    float2 f0 = __half22float2(*(__half2*)&v.x);
    float2 f1 = __half22float2(*(__half2*)&v.y);
    float2 f2 = __half22float2(*(__half2*)&v.z);
    float2 f3 = __half22float2(*(__half2*)&v.w);
    a[0] += f0.x + w0.x; a[1] += f0.y + w0.y;
    a[2] += f1.x + w0.z; a[3] += f1.y + w0.w;
    a[4] += f2.x + w1.x; a[5] += f2.y + w1.y;
    a[6] += f3.x + w1.z; a[7] += f3.y + w1.w;
}

__global__ void k_gather(const float* __restrict__ xbase, const float* __restrict__ W,
                         float* __restrict__ dout, const int* __restrict__ bid,
                         int final_pass) {
    int widx = (blockIdx.x * blockDim.x + threadIdx.x) >> 5;
    int lane = threadIdx.x & 31;
    if (widx >= NN) return;
    int n = widx;
    const float* bp;
    float* dst;
    if (final_pass) {
        bp = xbase + (size_t)n * CC;
        dst = dout + (size_t)n * CC;
    } else {
        bp = g_emb + (size_t)bid[n] * CC;
        dst = g_out1 + (size_t)n * CC;
    }
    float a[8];
    {
        float4 b0 = *(const float4*)(bp + lane * 8);
        float4 b1 = *(const float4*)(bp + lane * 8 + 4);
        a[0] = b0.x; a[1] = b0.y; a[2] = b0.z; a[3] = b0.w;
        a[4] = b1.x; a[5] = b1.y; a[6] = b1.z; a[7] = b1.w;
    }
    int e0 = g_off[n];
    int deg = g_off[n + 1] - e0;
    int dl = deg < 32 ? deg : 32;
    unsigned myp = (lane < dl) ? g_epack[e0 + lane] : 0u;   // coalesced batch read
    int i = 0;
    for (; i + 2 <= dl; i += 2) {
        unsigned p0 = __shfl_sync(0xFFFFFFFFu, myp, i);
        unsigned p1 = __shfl_sync(0xFFFFFFFFu, myp, i + 1);
        gacc(p0, W, lane, a);
        gacc(p1, W, lane, a);
    }
    if (i < dl) {
        unsigned p0 = __shfl_sync(0xFFFFFFFFu, myp, i);
        gacc(p0, W, lane, a);
    }
    for (int e = e0 + 32; e < e0 + deg; e++)                // rare deg>32 tail
        gacc(g_epack[e], W, lane, a);
    *(float4*)(dst + lane * 8)     = make_float4(a[0], a[1], a[2], a[3]);
    *(float4*)(dst + lane * 8 + 4) = make_float4(a[4], a[5], a[6], a[7]);
}

// ---------------- launcher ----------------
extern "C" void kernel_launch(void* const* d_in, const int* in_sizes, int n_in,
                              void* d_out, int out_size) {
    const float* x    = (const float*)d_in[0];
    const float* emb  = (const float*)d_in[1];
    const int*   bid  = (const int*)d_in[2];
    const int*   ei   = (const int*)d_in[3];
    const int*   et   = (const int*)d_in[4];
    const int*   ntp  = (const int*)d_in[5];
    const float* gn1w = (const float*)d_in[6];
    const float* gn1b = (const float*)d_in[7];
    const float* w1   = (const float*)d_in[8];
    const float* embw = (const float*)d_in[9];
    const float* embb = (const float*)d_in[10];
    const float* gn2w = (const float*)d_in[11];
    const float* gn2b = (const float*)d_in[12];
    const float* w2   = (const float*)d_in[13];
    float* out = (float*)d_out;

    static int s_attr = 0;
    if (!s_attr) {
        cudaFuncSetAttribute(k_gemm, cudaFuncAttributeMaxDynamicSharedMemorySize, GEMM_SMEM);
        s_attr = 1;
    }

    // CSR + compaction (shared by both convs) + emb
    k_zero_all<<<(NT7 + 255) / 256, 256>>>();
    k_degmark<<<EE / 256, 256>>>(ei, et);
    k_scanA<<<448, 256>>>();
    k_scanB<<<1, 448>>>();
    k_scanC<<<448, 256>>>();
    k_scan<<<1, 1024>>>();
    k_fill<<<EE / 256, 256>>>(ei, et, ntp);
    k_emb<<<BB, 256>>>(emb, embw, embb);

    // block 1
    k_stats<<<NN / 64, 256>>>(x, 0, bid, 1);
    k_fin<<<1, 256>>>();
    k_norm<<<NN / 2, 256>>>(x, 0, bid, gn1w, gn1b);
    k_wt<<<NET * 32 * 16 * 32 * 2 / 256, 256>>>(w1);
    k_gemm<<<dim3(2, 3584), 256, GEMM_SMEM>>>();
    k_gather<<<NN / 8, 256>>>(x, w1, out, bid, 0);

    // block 2
    k_stats<<<NN / 64, 256>>>(x, 1, bid, 0);
    k_fin<<<1, 256>>>();
    k_norm<<<NN / 2, 256>>>(x, 1, bid, gn2w, gn2b);
    k_wt<<<NET * 32 * 16 * 32 * 2 / 256, 256>>>(w2);
    k_gemm<<<dim3(2, 3584), 256, GEMM_SMEM>>>();
    k_gather<<<NN / 8, 256>>>(x, w2, out, bid, 1);
}

// round 13
// speedup vs baseline: 1.0334x; 1.0334x over previous
#include <cuda_runtime.h>
#include <cuda_fp16.h>
#include <cstdint>

// ---------------- problem constants ----------------
#define NN      65536
#define CC      256
#define BB      8
#define EMBD    512
#define NET     7
#define EE      458752
#define WROW    263
#define EPSV    1e-5f
#define NT7     (NN * NET)

// ---------------- device scratch ----------------
__device__ __align__(256) __half   g_hH[(size_t)(NN + 1) * CC];   // h row-major fp16 (+1 zero row)
__device__ __align__(256) uint32_t g_WtB[(size_t)NET * 32 * 16 * 32 * 2]; // B fp16 fragments
__device__ __align__(256) __half   g_Yh[(size_t)NT7 * CC];        // compact Y fp16 (worst case)
__device__ __align__(256) float    g_out1[(size_t)NN * CC];
__device__ float    g_S1[BB * CC];
__device__ float    g_S2[BB * CC];
__device__ float    g_cnt[BB];
__device__ float    g_mg[BB * 32];
__device__ float    g_istd[BB * 32];
__device__ __align__(256) float    g_emb[BB * CC];
__device__ int      g_deg[NN];
__device__ int      g_off[NN + 1];
__device__ int      g_cur[NN];
__device__ unsigned g_epack[EE];
// compaction structures
__device__ int      g_used[NT7];
__device__ int      g_pos[NT7];
__device__ int      g_rowmap[NT7];
__device__ int      g_bsum[448];
__device__ int      g_bbase[448];
__device__ int      g_tbase[8];
__device__ int      g_Mtot;

// ---------------- helpers ----------------
__device__ __forceinline__ float silu(float y) {
    return y / (1.f + __expf(-y));
}

__device__ __forceinline__ uint32_t smem_u32(const void* p) {
    uint32_t a;
    asm("{ .reg .u64 t; cvta.to.shared.u64 t, %1; cvt.u32.u64 %0, t; }" : "=r"(a) : "l"(p));
    return a;
}

__device__ __forceinline__ void cp16(uint32_t dst, const void* src) {
    asm volatile("cp.async.cg.shared.global [%0], [%1], 16;\n" :: "r"(dst), "l"(src));
}
__device__ __forceinline__ void cp_commit() { asm volatile("cp.async.commit_group;\n" ::: "memory"); }
__device__ __forceinline__ void cp_wait1()  { asm volatile("cp.async.wait_group 1;\n" ::: "memory"); }
__device__ __forceinline__ void cp_wait0()  { asm volatile("cp.async.wait_group 0;\n" ::: "memory"); }

__device__ __forceinline__ void mma_f16(float c[4], uint32_t a0, uint32_t a1,
                                        uint32_t a2, uint32_t a3,
                                        uint32_t b0, uint32_t b1) {
    asm volatile(
        "mma.sync.aligned.m16n8k16.row.col.f32.f16.f16.f32 "
        "{%0,%1,%2,%3}, {%4,%5,%6,%7}, {%8,%9}, {%0,%1,%2,%3};\n"
        : "+f"(c[0]), "+f"(c[1]), "+f"(c[2]), "+f"(c[3])
        : "r"(a0), "r"(a1), "r"(a2), "r"(a3), "r"(b0), "r"(b1));
}

// ---------------- zero / CSR / compaction kernels ----------------

__global__ void k_zero_all() {
    int i = blockIdx.x * blockDim.x + threadIdx.x;
    if (i < NT7)     { g_used[i] = 0; g_rowmap[i] = NN; }
    if (i < NN)      g_deg[i] = 0;
    if (i < BB * CC) { g_S1[i] = 0.f; g_S2[i] = 0.f; }
    if (i < BB)      g_cnt[i] = 0.f;
    if (i < 128)     ((uint32_t*)(g_hH + (size_t)NN * CC))[i] = 0;   // zero row
}

// merged degree count + used-pair mark (single edge pass)
__global__ void k_degmark(const int* __restrict__ ei, const int* __restrict__ et) {
    int e = blockIdx.x * blockDim.x + threadIdx.x;
    if (e >= EE) return;
    atomicAdd(&g_deg[ei[e]], 1);
    g_used[et[e] * NN + ei[EE + e]] = 1;
}

// stage A: per-1024-block sums of used flags (448 blocks)
__global__ void k_scanA() {
    __shared__ int sh[256];
    int b = blockIdx.x, tid = threadIdx.x;
    int base = b * 1024 + tid * 4;
    int s = g_used[base] + g_used[base + 1] + g_used[base + 2] + g_used[base + 3];
    sh[tid] = s;
    __syncthreads();
    for (int o = 128; o > 0; o >>= 1) {
        if (tid < o) sh[tid] += sh[tid + o];
        __syncthreads();
    }
    if (tid == 0) g_bsum[b] = sh[0];
}

// stage B (parallel): per-type block-base scan + padded type bases
__global__ void k_scanB() {
    __shared__ int sh[448];
    __shared__ int tsum[NET];
    int tid = threadIdx.x;          // 0..447
    int t = tid >> 6, l = tid & 63;
    int v = g_bsum[tid];
    sh[tid] = v;
    __syncthreads();
    for (int o = 1; o < 64; o <<= 1) {
        int u = (l >= o) ? sh[tid - o] : 0;
        __syncthreads();
        sh[tid] += u;
        __syncthreads();
    }
    if (l == 63) tsum[t] = sh[tid];
    __syncthreads();
    if (tid == 0) {
        int mt = 0;
#pragma unroll
        for (int tt = 0; tt < NET; tt++) {
            g_tbase[tt] = mt;
            mt += (tsum[tt] + 127) & ~127;
        }
        g_tbase[NET] = mt;
        g_Mtot = mt;
    }
    g_bbase[tid] = sh[tid] - v;     // exclusive within type group
}

// stage C: per-element positions + rowmap
__global__ void k_scanC() {
    __shared__ int sh[256];
    int b = blockIdx.x, tid = threadIdx.x, t = b >> 6;
    int base = b * 1024 + tid * 4;
    int f0 = g_used[base], f1 = g_used[base + 1], f2 = g_used[base + 2], f3 = g_used[base + 3];
    int s = f0 + f1 + f2 + f3;
    sh[tid] = s;
    __syncthreads();
    for (int o = 1; o < 256; o <<= 1) {
        int v = (tid >= o) ? sh[tid - o] : 0;
        __syncthreads();
        sh[tid] += v;
        __syncthreads();
    }
    int run = g_bbase[b] + ((tid == 0) ? 0 : sh[tid - 1]);
    int tb = g_tbase[t];
    int cbase = base - t * NN;
    if (f0) { g_pos[base]     = run; g_rowmap[tb + run] = cbase;     run++; }
    if (f1) { g_pos[base + 1] = run; g_rowmap[tb + run] = cbase + 1; run++; }
    if (f2) { g_pos[base + 2] = run; g_rowmap[tb + run] = cbase + 2; run++; }
    if (f3) { g_pos[base + 3] = run; g_rowmap[tb + run] = cbase + 3; run++; }
}

// scan destination-row degrees -> CSR offsets
__global__ void k_scan() {
    __shared__ int ps[1024];
    int t = threadIdx.x;
    int s = 0;
#pragma unroll 8
    for (int i = 0; i < 64; i++) s += g_deg[t * 64 + i];
    ps[t] = s;
    __syncthreads();
    for (int off = 1; off < 1024; off <<= 1) {
        int v = (t >= off) ? ps[t - off] : 0;
        __syncthreads();
        ps[t] += v;
        __syncthreads();
    }
    int run = (t == 0) ? 0 : ps[t - 1];
    for (int i = 0; i < 64; i++) {
        int d = g_deg[t * 64 + i];
        g_off[t * 64 + i] = run;
        g_cur[t * 64 + i] = run;
        run += d;
    }
    if (t == 1023) g_off[NN] = run;
}

// fill CSR payload: gpos(19b) | t(3b) | nt(3b)
__global__ void k_fill(const int* __restrict__ ei, const int* __restrict__ et,
                       const int* __restrict__ ntp) {
    int e = blockIdx.x * blockDim.x + threadIdx.x;
    if (e >= EE) return;
    int r = ei[e];
    int c = ei[EE + e];
    int t = et[e];
    int nt = ntp[c];
    int gpos = g_tbase[t] + g_pos[t * NN + c];
    int pos = atomicAdd(&g_cur[r], 1);
    g_epack[pos] = (unsigned)gpos | ((unsigned)t << 19) | ((unsigned)nt << 22);
}

__global__ void k_emb(const float* __restrict__ emb, const float* __restrict__ ew,
                      const float* __restrict__ eb) {
    __shared__ float se[EMBD];
    int b = blockIdx.x;
    int j = threadIdx.x;
    for (int k = j; k < EMBD; k += 256) se[k] = silu(emb[b * EMBD + k]);
    __syncthreads();
    float acc = eb[j];
#pragma unroll 8
    for (int k = 0; k < EMBD; k++) acc = fmaf(se[k], ew[k * CC + j], acc);
    g_emb[b * CC + j] = acc;
}

__global__ void k_stats(const float* __restrict__ src, int use_out1,
                        const int* __restrict__ bid, int do_cnt) {
    const float* s = use_out1 ? g_out1 : src;
    int c = threadIdx.x;
    int r0 = blockIdx.x * 64;
    float s1 = 0.f, s2 = 0.f;
    int cb = bid[r0];
    int cl = 0;
    for (int i = 0; i < 64; i++) {
        int r = r0 + i;
        int b = bid[r];
        if (b != cb) {
            atomicAdd(&g_S1[cb * CC + c], s1);
            atomicAdd(&g_S2[cb * CC + c], s2);
            if (do_cnt && c == 0) atomicAdd(&g_cnt[cb], (float)cl);
            s1 = 0.f; s2 = 0.f; cl = 0; cb = b;
        }
        float v = s[(size_t)r * CC + c];
        s1 += v;
        s2 = fmaf(v, v, s2);
        cl++;
    }
    atomicAdd(&g_S1[cb * CC + c], s1);
    atomicAdd(&g_S2[cb * CC + c], s2);
    if (do_cnt && c == 0) atomicAdd(&g_cnt[cb], (float)cl);
}

// finalize group stats; re-zero S1/S2 for the next pass (saves a launch)
__global__ void k_fin() {
    int t = threadIdx.x;
    int b = t >> 5, g = t & 31;
    float gs1 = 0.f, gs2 = 0.f;
#pragma unroll
    for (int i = 0; i < 8; i++) {
        gs1 += g_S1[b * CC + g * 8 + i];
        gs2 += g_S2[b * CC + g * 8 + i];
    }
    float n = g_cnt[b] * 8.f;
    float inv = 1.f / (n + EPSV);
    float m = gs1 * inv;
    float var = (gs2 - 2.f * m * gs1 + n * m * m) * inv;
    g_mg[b * 32 + g] = m;
    g_istd[b * 32 + g] = rsqrtf(var + EPSV);
#pragma unroll
    for (int i = 0; i < 8; i++) {
        g_S1[b * CC + g * 8 + i] = 0.f;
        g_S2[b * CC + g * 8 + i] = 0.f;
    }
}

// h = fp16( silu( gn(x) ) ), row-major
__global__ void k_norm(const float* __restrict__ src, int use_out1,
                       const int* __restrict__ bid, const float* __restrict__ w,
                       const float* __restrict__ bbv) {
    const float* sp = use_out1 ? g_out1 : src;
    int n = blockIdx.x * 2 + (threadIdx.x >> 7);
    int cp2 = threadIdx.x & 127;
    int c0 = cp2 * 2;
    int b = bid[n];
    int g = c0 >> 3;
    float m = g_mg[b * 32 + g];
    float is = g_istd[b * 32 + g];
    float2 v = *(const float2*)(sp + (size_t)n * CC + c0);
    float y0 = silu((v.x - m) * is * w[c0] + bbv[c0]);
    float y1 = silu((v.y - m) * is * w[c0 + 1] + bbv[c0 + 1]);
    ((__half2*)g_hH)[(size_t)n * 128 + cp2] = __floats2half2_rn(y0, y1);
}

// W[t][k][n] -> fp16 B-fragment layout
__global__ void k_wt(const float* __restrict__ W) {
    int g = blockIdx.x * blockDim.x + threadIdx.x;
    if (g >= NET * 32 * 16 * 32 * 2) return;
    int breg = g & 1;
    int lane = (g >> 1) & 31;
    int kt = (g >> 6) & 15;
    int nt = (g >> 10) & 31;
    int t = g >> 15;
    int k = kt * 16 + (lane & 3) * 2 + breg * 8;
    int n = nt * 8 + (lane >> 2);
    float v0 = W[(size_t)(t * WROW + k) * CC + n];
    float v1 = W[(size_t)(t * WROW + k + 1) * CC + n];
    __half2 h2 = __floats2half2_rn(v0, v1);
    g_WtB[(size_t)g] = *(uint32_t*)&h2;
}

// -------- compacted fp16 GEMM (R9 form) --------
#define GEMM_SMEM 66048

__device__ __forceinline__ void cpA(uint4* sA, const int* __restrict__ srow, int kc, int tid) {
#pragma unroll
    for (int i = 0; i < 4; i++) {
        int idx = i * 256 + tid;
        int r = idx >> 3, u = idx & 7;
        const __half* src = g_hH + (size_t)srow[r] * CC + kc * 64 + u * 8;
        cp16(smem_u32(sA + r * 8 + (u ^ (r & 7))), src);
    }
}

__device__ __forceinline__ void cpB(uint32_t* sB, const uint32_t* gB, int c, int tid) {
#pragma unroll
    for (int i = 0; i < 4; i++) {
        int idx = i * 256 + tid;
        int nt = idx >> 6, rest = idx & 63;
        int ktl = rest >> 4, u = rest & 15;
        const uint32_t* src = gB + ((size_t)nt * 16 + c * 4 + ktl) * 64 + u * 4;
        cp16(smem_u32(sB + ((nt * 4 + ktl) * 64 + u * 4)), src);
    }
}

__device__ __forceinline__ void compute_chunk(const uint4* sA, const uint32_t* sB,
                                              float c[2][8][4], int wm, int wn, int lane) {
#pragma unroll
    for (int ktl = 0; ktl < 4; ktl++) {
        uint32_t a[2][4];
#pragma unroll
        for (int mm = 0; mm < 2; mm++) {
            int r = wm * 32 + mm * 16 + (lane & 15);
            int grp = (ktl * 2 + (lane >> 4)) ^ (r & 7);
            uint32_t addr = smem_u32(sA + r * 8 + grp);
            asm volatile("ldmatrix.sync.aligned.m8n8.x4.shared.b16 {%0,%1,%2,%3}, [%4];"
                         : "=r"(a[mm][0]), "=r"(a[mm][1]), "=r"(a[mm][2]), "=r"(a[mm][3])
                         : "r"(addr));
        }
#pragma unroll
        for (int nn = 0; nn < 8; nn++) {
            uint2 b = *(const uint2*)(sB + ((wn * 8 + nn) * 4 + ktl) * 64 + lane * 2);
            mma_f16(c[0][nn], a[0][0], a[0][1], a[0][2], a[0][3], b.x, b.y);
            mma_f16(c[1][nn], a[1][0], a[1][1], a[1][2], a[1][3], b.x, b.y);
        }
    }
}

__global__ void __launch_bounds__(256, 2) k_gemm() {
    extern __shared__ uint32_t sm[];
    uint4*    A0 = (uint4*)sm;             // 16KB
    uint4*    A1 = (uint4*)(sm + 4096);    // 16KB
    uint32_t* B0 = sm + 8192;              // 16KB
    uint32_t* B1 = sm + 12288;             // 16KB
    int*      srow = (int*)(sm + 16384);   // 512B

    int m0 = blockIdx.y * 128;
    if (m0 >= g_Mtot) return;
    int t = 0;
    while (m0 >= g_tbase[t + 1]) t++;

    int tid = threadIdx.x;
    int lane = tid & 31, warp = tid >> 5;
    int wm = warp & 3, wn = warp >> 2;
    int ntile = blockIdx.x;
    int n0 = ntile * 128;

    if (tid < 128) srow[tid] = g_rowmap[m0 + tid];
    __syncthreads();

    const uint32_t* gB = g_WtB + ((size_t)t * 32 + ntile * 16) * 16 * 64;

    float c[2][8][4];
#pragma unroll
    for (int mm = 0; mm < 2; mm++)
#pragma unroll
        for (int nn = 0; nn < 8; nn++)
#pragma unroll
            for (int q = 0; q < 4; q++) c[mm][nn][q] = 0.f;

    cpA(A0, srow, 0, tid); cpB(B0, gB, 0, tid); cp_commit();
    cpA(A1, srow, 1, tid); cpB(B1, gB, 1, tid); cp_commit();

    cp_wait1(); __syncthreads();
    compute_chunk(A0, B0, c, wm, wn, lane);
    __syncthreads();
    cpA(A0, srow, 2, tid); cpB(B0, gB, 2, tid); cp_commit();

    cp_wait1(); __syncthreads();
    compute_chunk(A1, B1, c, wm, wn, lane);
    __syncthreads();
    cpA(A1, srow, 3, tid); cpB(B1, gB, 3, tid); cp_commit();

    cp_wait1(); __syncthreads();
    compute_chunk(A0, B0, c, wm, wn, lane);

    cp_wait0(); __syncthreads();
    compute_chunk(A1, B1, c, wm, wn, lane);

    // epilogue -> compact fp16 Y
    int gid = lane >> 2, tig = lane & 3;
    __half* Yb = g_Yh + (size_t)m0 * CC + n0;
#pragma unroll
    for (int mm = 0; mm < 2; mm++) {
#pragma unroll
        for (int nn = 0; nn < 8; nn++) {
            int r = wm * 32 + mm * 16 + gid;
            int cc2 = wn * 64 + nn * 8 + tig * 2;
            *(__half2*)(Yb + (size_t)r * CC + cc2)       = __floats2half2_rn(c[mm][nn][0], c[mm][nn][1]);
            *(__half2*)(Yb + (size_t)(r + 8) * CC + cc2) = __floats2half2_rn(c[mm][nn][2], c[mm][nn][3]);
        }
    }
}

// warp-per-node gather over compact Y (R9 form — proven fastest)
__global__ void k_gather(const float* __restrict__ xbase, const float* __restrict__ W,
                         float* __restrict__ dout, const int* __restrict__ bid,
                         int final_pass) {
    int widx = (blockIdx.x * blockDim.x + threadIdx.x) >> 5;
    int lane = threadIdx.x & 31;
    if (widx >= NN) return;
    int n = widx;
    const float* bp;
    float* dst;
    if (final_pass) {
        bp = xbase + (size_t)n * CC;
        dst = dout + (size_t)n * CC;
    } else {
        bp = g_emb + (size_t)bid[n] * CC;
        dst = g_out1 + (size_t)n * CC;
    }
    float a[8];
    {
        float4 b0 = *(const float4*)(bp + lane * 8);
        float4 b1 = *(const float4*)(bp + lane * 8 + 4);
        a[0] = b0.x; a[1] = b0.y; a[2] = b0.z; a[3] = b0.w;
        a[4] = b1.x; a[5] = b1.y; a[6] = b1.z; a[7] = b1.w;
    }
    int e0 = g_off[n], e1 = g_off[n + 1];
    for (int e = e0; e < e1; e++) {
        unsigned p = g_epack[e];
        int gpos = p & 0x7FFFF;
        int t = (p >> 19) & 7;
        int nt = (p >> 22) & 7;
        const uint4* y = (const uint4*)(g_Yh + (size_t)gpos * CC) + lane;
        uint4 v = __ldg(y);
        float2 f0 = __half22float2(*(__half2*)&v.x);
        float2 f1 = __half22float2(*(__half2*)&v.y);
        float2 f2 = __half22float2(*(__half2*)&v.z);
        float2 f3 = __half22float2(*(__half2*)&v.w);
        const float* wr = W + (size_t)(t * WROW + CC + nt) * CC + lane * 8;
        float4 w0 = *(const float4*)wr;
        float4 w1 = *(const float4*)(wr + 4);
        a[0] += f0.x + w0.x; a[1] += f0.y + w0.y;
        a[2] += f1.x + w0.z; a[3] += f1.y + w0.w;
        a[4] += f2.x + w1.x; a[5] += f2.y + w1.y;
        a[6] += f3.x + w1.z; a[7] += f3.y + w1.w;
    }
    *(float4*)(dst + lane * 8)     = make_float4(a[0], a[1], a[2], a[3]);
    *(float4*)(dst + lane * 8 + 4) = make_float4(a[4], a[5], a[6], a[7]);
}

// ---------------- launcher ----------------
extern "C" void kernel_launch(void* const* d_in, const int* in_sizes, int n_in,
                              void* d_out, int out_size) {
    const float* x    = (const float*)d_in[0];
    const float* emb  = (const float*)d_in[1];
    const int*   bid  = (const int*)d_in[2];
    const int*   ei   = (const int*)d_in[3];
    const int*   et   = (const int*)d_in[4];
    const int*   ntp  = (const int*)d_in[5];
    const float* gn1w = (const float*)d_in[6];
    const float* gn1b = (const float*)d_in[7];
    const float* w1   = (const float*)d_in[8];
    const float* embw = (const float*)d_in[9];
    const float* embb = (const float*)d_in[10];
    const float* gn2w = (const float*)d_in[11];
    const float* gn2b = (const float*)d_in[12];
    const float* w2   = (const float*)d_in[13];
    float* out = (float*)d_out;

    static int s_attr = 0;
    if (!s_attr) {
        cudaFuncSetAttribute(k_gemm, cudaFuncAttributeMaxDynamicSharedMemorySize, GEMM_SMEM);
        s_attr = 1;
    }

    // CSR + compaction (shared by both convs) + emb
    k_zero_all<<<(NT7 + 255) / 256, 256>>>();
    k_degmark<<<EE / 256, 256>>>(ei, et);
    k_scanA<<<448, 256>>>();
    k_scanB<<<1, 448>>>();
    k_scanC<<<448, 256>>>();
    k_scan<<<1, 1024>>>();
    k_fill<<<EE / 256, 256>>>(ei, et, ntp);
    k_emb<<<BB, 256>>>(emb, embw, embb);

    // block 1
    k_stats<<<NN / 64, 256>>>(x, 0, bid, 1);
    k_fin<<<1, 256>>>();
    k_norm<<<NN / 2, 256>>>(x, 0, bid, gn1w, gn1b);
    k_wt<<<NET * 32 * 16 * 32 * 2 / 256, 256>>>(w1);
    k_gemm<<<dim3(2, 3584), 256, GEMM_SMEM>>>();
    k_gather<<<NN / 8, 256>>>(x, w1, out, bid, 0);

    // block 2
    k_stats<<<NN / 64, 256>>>(x, 1, bid, 0);
    k_fin<<<1, 256>>>();
    k_norm<<<NN / 2, 256>>>(x, 1, bid, gn2w, gn2b);
    k_wt<<<NET * 32 * 16 * 32 * 2 / 256, 256>>>(w2);
    k_gemm<<<dim3(2, 3584), 256, GEMM_SMEM>>>();
    k_gather<<<NN / 8, 256>>>(x, w2, out, bid, 1);
}